// round 5
// baseline (speedup 1.0000x reference)
#include <cuda_runtime.h>
#include <cuda_bf16.h>

// ---------------------------------------------------------------------------
// CorrelationHead: corr(patch1,patch2) -> FC1(relu) -> FC2(relu) -> FC3
// Sparse structural fact: with P=16, DIL=2, H=7, only 625 of 12544
// correlation features are ever nonzero (25 valid (i,i2) row pairs x 25
// valid (j,j2) col pairs). We compute only those, gather the matching 625
// columns of W1, and run FC1 as a 1024x1024x640 GEMM (zero-padded to 640).
// ---------------------------------------------------------------------------

#define B_ROIS 1024
#define KPAD   640      // 625 valid features padded to 640 (mult of 16)
#define REP    1024

// (i, i2) pairs enumerated in (ph ascending, i ascending) order; i2 = i + 2*(ph-7).
// Same table serves the (j, j2)/(pw) dimension by symmetry.
__device__ const int d_AI [25] = {6, 4,5,6, 2,3,4,5,6, 0,1,2,3,4,5,6, 0,1,2,3,4, 0,1,2, 0};
__device__ const int d_AI2[25] = {0, 0,1,2, 0,1,2,3,4, 0,1,2,3,4,5,6, 2,3,4,5,6, 4,5,6, 6};

// Scratch (device globals; no runtime allocation allowed).
__device__ float g_W1g[KPAD * REP];        // gathered W1, layout [n][k] (N-major)
__device__ float g_corr[B_ROIS * KPAD];    // compact correlation [b][k]
__device__ float g_Y1[B_ROIS * REP];
__device__ float g_Y2[B_ROIS * REP];

// ---------------------------------------------------------------------------
// Gather the 625 useful W1 columns into g_W1g[n][k] (zero pad k=625..639).
// ---------------------------------------------------------------------------
__global__ void gather_w1_kernel(const float* __restrict__ W1, float* __restrict__ W1g)
{
    int idx = blockIdx.x * 256 + threadIdx.x;
    if (idx >= REP * KPAD) return;
    int n = idx / KPAD;
    int k = idx - n * KPAD;
    float v = 0.f;
    if (k < 625) {
        int a  = k / 25;
        int bc = k - a * 25;
        int i  = d_AI[a],  i2 = d_AI2[a];
        int j  = d_AI[bc], j2 = d_AI2[bc];
        int ph = 7 + ((i2 - i) >> 1);
        int pw = 7 + ((j2 - j) >> 1);
        int f  = (ph * 16 + pw) * 49 + i * 7 + j;
        v = W1[n * 12544 + f];
    }
    W1g[idx] = v;
}

// ---------------------------------------------------------------------------
// Correlation (compact). One CTA per RoI; both 256x7x7 patches in smem.
// Warp w handles channels [32w, 32w+32); lane (<25) handles one (pw,j) column
// pair; per channel it loads 7 x1 values (column j) and 7 x2 values (column
// j2) and does a 25-term outer product over the valid (i,i2) pairs.
// 8 partial sums reduced through smem.
// ---------------------------------------------------------------------------
#define CORR_SMEM (2 * 12544 * 4)

__global__ void __launch_bounds__(256) corr_kernel(const float* __restrict__ p1,
                                                   const float* __restrict__ p2,
                                                   float* __restrict__ corr)
{
    extern __shared__ float sm[];
    float* s1 = sm;
    float* s2 = sm + 12544;

    int b   = blockIdx.x;
    int tid = threadIdx.x;
    const float4* g1 = (const float4*)(p1 + b * 12544);
    const float4* g2 = (const float4*)(p2 + b * 12544);
    for (int i = tid; i < 3136; i += 256) {   // 12544 floats = 3136 float4
        ((float4*)s1)[i] = g1[i];
        ((float4*)s2)[i] = g2[i];
    }
    __syncthreads();

    int warp = tid >> 5, lane = tid & 31;
    float acc[25];
    if (lane < 25) {
        // compile-time (i,i2) tables so acc[] indexing stays in registers
        constexpr int AI [25] = {6, 4,5,6, 2,3,4,5,6, 0,1,2,3,4,5,6, 0,1,2,3,4, 0,1,2, 0};
        constexpr int AI2[25] = {0, 0,1,2, 0,1,2,3,4, 0,1,2,3,4,5,6, 2,3,4,5,6, 4,5,6, 6};
        int j  = d_AI[lane];
        int j2 = d_AI2[lane];
#pragma unroll
        for (int a = 0; a < 25; ++a) acc[a] = 0.f;
        const float* s1w = s1 + warp * 32 * 49 + j;
        const float* s2w = s2 + warp * 32 * 49 + j2;
#pragma unroll 4
        for (int cc = 0; cc < 32; ++cc) {
            float v1[7], v2[7];
#pragma unroll
            for (int i = 0; i < 7; ++i) {
                v1[i] = s1w[cc * 49 + i * 7];
                v2[i] = s2w[cc * 49 + i * 7];
            }
#pragma unroll
            for (int a = 0; a < 25; ++a)
                acc[a] = fmaf(v1[AI[a]], v2[AI2[a]], acc[a]);
        }
    }
    __syncthreads();           // all smem reads done; reuse s1 region for reduce

    float* red = sm;           // [25][8 warps * 32 lanes] = 6400 floats
    if (lane < 25) {
#pragma unroll
        for (int a = 0; a < 25; ++a)
            red[a * 256 + warp * 32 + lane] = acc[a];
    }
    __syncthreads();

    for (int k = tid; k < 625; k += 256) {
        int a  = k / 25;
        int bc = k - a * 25;
        float s = 0.f;
#pragma unroll
        for (int w = 0; w < 8; ++w) s += red[a * 256 + w * 32 + bc];
        corr[b * KPAD + k] = s;
    }
    if (tid < KPAD - 625) corr[b * KPAD + 625 + tid] = 0.f;
}

// ---------------------------------------------------------------------------
// SGEMM (double-buffered): C[m][n] = sum_k A[m][k]*Bt[n][k] + bias[n], opt ReLU.
// A: [M][K] row-major, Bt: [N][K] row-major (torch-Linear weight layout).
// 64x64x16 tiles, 128 threads, 8x4 microtile. Per k-tile: prefetch next
// tile's LDGs into registers, compute current smem buffer, STS into the
// alternate buffer, one __syncthreads. K mult of 16; M,N mult of 64.
// ---------------------------------------------------------------------------
template <bool RELU>
__global__ void __launch_bounds__(128) sgemm_tn(const float* __restrict__ A,
                                                const float* __restrict__ Bt,
                                                const float* __restrict__ bias,
                                                float* __restrict__ C,
                                                int M, int N, int K)
{
    __shared__ float As[2][16][68];
    __shared__ float Bs[2][16][68];

    int tid = threadIdx.x;
    int bx = blockIdx.x, by = blockIdx.y;
    const float* Ab = A  + (size_t)by * 64 * K;
    const float* Bb = Bt + (size_t)bx * 64 * K;

    int loadRow = tid >> 2;          // 0..31 (rows r and r+32)
    int loadK   = (tid & 3) * 4;     // 0,4,8,12
    int tx = tid & 15;               // n-tile (TN=4)
    int ty = tid >> 4;               // m-tile (TM=8)

    float acc[8][4];
#pragma unroll
    for (int m = 0; m < 8; ++m)
#pragma unroll
        for (int n = 0; n < 4; ++n) acc[m][n] = 0.f;

    // Prologue: load k-tile 0 into buffer 0.
#pragma unroll
    for (int p = 0; p < 2; ++p) {
        int r = loadRow + p * 32;
        float4 a = *(const float4*)&Ab[(size_t)r * K + loadK];
        As[0][loadK + 0][r] = a.x; As[0][loadK + 1][r] = a.y;
        As[0][loadK + 2][r] = a.z; As[0][loadK + 3][r] = a.w;
        float4 bv = *(const float4*)&Bb[(size_t)r * K + loadK];
        Bs[0][loadK + 0][r] = bv.x; Bs[0][loadK + 1][r] = bv.y;
        Bs[0][loadK + 2][r] = bv.z; Bs[0][loadK + 3][r] = bv.w;
    }
    __syncthreads();

    int buf = 0;
    for (int kt = 0; kt < K; kt += 16) {
        // Prefetch next k-tile into registers (overlaps with compute below).
        float4 pa[2], pb[2];
        bool has_next = (kt + 16) < K;
        if (has_next) {
#pragma unroll
            for (int p = 0; p < 2; ++p) {
                int r = loadRow + p * 32;
                pa[p] = *(const float4*)&Ab[(size_t)r * K + kt + 16 + loadK];
                pb[p] = *(const float4*)&Bb[(size_t)r * K + kt + 16 + loadK];
            }
        }

        // Compute on current buffer.
#pragma unroll
        for (int k = 0; k < 16; ++k) {
            float av[8], bv[4];
#pragma unroll
            for (int m = 0; m < 8; ++m) av[m] = As[buf][k][ty * 8 + m];
#pragma unroll
            for (int n = 0; n < 4; ++n) bv[n] = Bs[buf][k][tx * 4 + n];
#pragma unroll
            for (int m = 0; m < 8; ++m)
#pragma unroll
                for (int n = 0; n < 4; ++n)
                    acc[m][n] = fmaf(av[m], bv[n], acc[m][n]);
        }

        // Stage prefetched tile into the alternate buffer.
        if (has_next) {
            int nbuf = buf ^ 1;
#pragma unroll
            for (int p = 0; p < 2; ++p) {
                int r = loadRow + p * 32;
                As[nbuf][loadK + 0][r] = pa[p].x; As[nbuf][loadK + 1][r] = pa[p].y;
                As[nbuf][loadK + 2][r] = pa[p].z; As[nbuf][loadK + 3][r] = pa[p].w;
                Bs[nbuf][loadK + 0][r] = pb[p].x; Bs[nbuf][loadK + 1][r] = pb[p].y;
                Bs[nbuf][loadK + 2][r] = pb[p].z; Bs[nbuf][loadK + 3][r] = pb[p].w;
            }
            __syncthreads();
            buf = nbuf;
        }
    }

    int gn0 = bx * 64 + tx * 4;
    float4 bias4 = *(const float4*)&bias[gn0];
    float bb[4] = {bias4.x, bias4.y, bias4.z, bias4.w};
#pragma unroll
    for (int m = 0; m < 8; ++m) {
        int gm = by * 64 + ty * 8 + m;
        float4 o;
        float v0 = acc[m][0] + bb[0], v1 = acc[m][1] + bb[1];
        float v2 = acc[m][2] + bb[2], v3 = acc[m][3] + bb[3];
        if (RELU) {
            v0 = fmaxf(v0, 0.f); v1 = fmaxf(v1, 0.f);
            v2 = fmaxf(v2, 0.f); v3 = fmaxf(v3, 0.f);
        }
        o.x = v0; o.y = v1; o.z = v2; o.w = v3;
        *(float4*)&C[(size_t)gm * N + gn0] = o;
    }
}

// ---------------------------------------------------------------------------
// FC3: out[b][o] = dot(Y2[b], W3[o]) + b3[o].  One block per RoI, 4 warps.
// ---------------------------------------------------------------------------
__global__ void __launch_bounds__(128) fc3_kernel(const float* __restrict__ Y,
                                                  const float* __restrict__ W3,
                                                  const float* __restrict__ b3,
                                                  float* __restrict__ out)
{
    int b = blockIdx.x;
    int warp = threadIdx.x >> 5, lane = threadIdx.x & 31;
    const float* y = Y  + (size_t)b * REP;
    const float* w = W3 + (size_t)warp * REP;
    float s = 0.f;
#pragma unroll 8
    for (int k = lane; k < REP; k += 32) s = fmaf(y[k], w[k], s);
#pragma unroll
    for (int off = 16; off > 0; off >>= 1)
        s += __shfl_down_sync(0xffffffff, s, off);
    if (lane == 0) out[b * 4 + warp] = s + b3[warp];
}

// ---------------------------------------------------------------------------
extern "C" void kernel_launch(void* const* d_in, const int* in_sizes, int n_in,
                              void* d_out, int out_size)
{
    const float* patch1 = (const float*)d_in[0];
    const float* patch2 = (const float*)d_in[1];
    const float* W1     = (const float*)d_in[2];
    const float* b1     = (const float*)d_in[3];
    const float* W2     = (const float*)d_in[4];
    const float* b2     = (const float*)d_in[5];
    const float* W3     = (const float*)d_in[6];
    const float* b3     = (const float*)d_in[7];
    float* out = (float*)d_out;

    float *pW1g, *pCorr, *pY1, *pY2;
    cudaGetSymbolAddress((void**)&pW1g, g_W1g);
    cudaGetSymbolAddress((void**)&pCorr, g_corr);
    cudaGetSymbolAddress((void**)&pY1, g_Y1);
    cudaGetSymbolAddress((void**)&pY2, g_Y2);

    cudaFuncSetAttribute(corr_kernel,
                         cudaFuncAttributeMaxDynamicSharedMemorySize, CORR_SMEM);

    gather_w1_kernel<<<(REP * KPAD + 255) / 256, 256>>>(W1, pW1g);
    corr_kernel<<<B_ROIS, 256, CORR_SMEM>>>(patch1, patch2, pCorr);
    sgemm_tn<true><<<dim3(16, 16), 128>>>(pCorr, pW1g, b1, pY1, B_ROIS, REP, KPAD);
    sgemm_tn<true><<<dim3(16, 16), 128>>>(pY1, W2, b2, pY2, B_ROIS, REP, REP);
    fc3_kernel<<<B_ROIS, 128>>>(pY2, W3, b3, out);
}